// round 1
// baseline (speedup 1.0000x reference)
#include <cuda_runtime.h>
#include <cuda_bf16.h>

#define N_ATOMS   5000
#define N_EDGES   200000
#define N_TRIPLES 4000000
#define D_NODE    128
#define D_EDGE    128
#define N_BASIS   9

// Scratch (no allocations allowed)
__device__ float g_atoms[N_ATOMS * N_BASIS];        // sigmoid(node@W_atom+b)  [5000 x 9]
__device__ float g_new_bonds[N_EDGES * N_BASIS];    // segment sums            [200000 x 9]

// ---------------------------------------------------------------------------
// Kernel 0: zero the segment-sum accumulator
// ---------------------------------------------------------------------------
__global__ void zero_bonds_kernel() {
    int i = blockIdx.x * blockDim.x + threadIdx.x;
    const int n4 = (N_EDGES * N_BASIS) / 4;  // 450000
    if (i < n4) reinterpret_cast<float4*>(g_new_bonds)[i] = make_float4(0.f, 0.f, 0.f, 0.f);
}

// ---------------------------------------------------------------------------
// Kernel 1: atoms = sigmoid(node_feat @ W_atom + b_atom)   [5000 x 9]
// Thread per (atom, basis) pair.
// ---------------------------------------------------------------------------
__global__ void atoms_kernel(const float* __restrict__ node_feat,
                             const float* __restrict__ W_atom,
                             const float* __restrict__ b_atom) {
    int id = blockIdx.x * blockDim.x + threadIdx.x;
    if (id >= N_ATOMS * N_BASIS) return;
    int a = id / N_BASIS;
    int j = id % N_BASIS;
    float acc = b_atom[j];
    const float* nf = node_feat + a * D_NODE;
    #pragma unroll 8
    for (int k = 0; k < D_NODE; k++)
        acc = fmaf(nf[k], W_atom[k * N_BASIS + j], acc);
    g_atoms[id] = 1.0f / (1.0f + __expf(-acc));
}

// ---------------------------------------------------------------------------
// Kernel 2: basis = three_basis * atoms[graph_dst[lg_dst]]; segment_sum -> g_new_bonds
//
// - atoms table (180 KB) staged into dynamic shared memory (one copy/block)
// - each thread owns 16 CONTIGUOUS triples (segment_ids sorted -> long runs),
//   streams three_basis with aligned float4 loads, accumulates the 9-vector in
//   registers, and flushes with atomicAdd (RED) only on segment change.
// ---------------------------------------------------------------------------
#define TPB_B   512
#define GRID_B  148
#define CHUNK   16
#define NCHUNKS (N_TRIPLES / CHUNK)   // 250000, exact

__global__ __launch_bounds__(TPB_B) void triples_kernel(
    const float* __restrict__ three_basis,
    const int*   __restrict__ graph_dst,
    const int*   __restrict__ lg_dst,
    const int*   __restrict__ seg_ids) {

    extern __shared__ float s_atoms[];  // 45000 floats = 180000 bytes
    for (int i = threadIdx.x; i < N_ATOMS * N_BASIS; i += TPB_B)
        s_atoms[i] = g_atoms[i];
    __syncthreads();

    const float4* tb4 = reinterpret_cast<const float4*>(three_basis);
    const int4*   lg4 = reinterpret_cast<const int4*>(lg_dst);
    const int4*   sg4 = reinterpret_cast<const int4*>(seg_ids);

    int tid = blockIdx.x * TPB_B + threadIdx.x;
    const int stride = GRID_B * TPB_B;

    for (int chunk = tid; chunk < NCHUNKS; chunk += stride) {
        float acc[N_BASIS];
        #pragma unroll
        for (int j = 0; j < N_BASIS; j++) acc[j] = 0.f;
        int cur = -1;

        #pragma unroll
        for (int s = 0; s < 4; s++) {           // 4 subgroups of 4 triples
            int4 lg = lg4[chunk * 4 + s];
            int4 sg = sg4[chunk * 4 + s];
            int eis[4];
            eis[0] = graph_dst[lg.x];
            eis[1] = graph_dst[lg.y];
            eis[2] = graph_dst[lg.z];
            eis[3] = graph_dst[lg.w];
            int segs[4] = {sg.x, sg.y, sg.z, sg.w};

            // 4 triples * 9 floats = 36 floats = 9 aligned float4 loads
            float v[36];
            #pragma unroll
            for (int i = 0; i < 9; i++) {
                float4 t = tb4[chunk * 36 + s * 9 + i];
                v[i * 4 + 0] = t.x; v[i * 4 + 1] = t.y;
                v[i * 4 + 2] = t.z; v[i * 4 + 3] = t.w;
            }

            #pragma unroll
            for (int t = 0; t < 4; t++) {
                int e = segs[t];
                if (e != cur) {
                    if (cur >= 0) {
                        float* dst = g_new_bonds + cur * N_BASIS;
                        #pragma unroll
                        for (int j = 0; j < N_BASIS; j++) atomicAdd(dst + j, acc[j]);
                        #pragma unroll
                        for (int j = 0; j < N_BASIS; j++) acc[j] = 0.f;
                    }
                    cur = e;
                }
                const float* arow = s_atoms + eis[t] * N_BASIS;
                #pragma unroll
                for (int j = 0; j < N_BASIS; j++)
                    acc[j] = fmaf(v[t * 9 + j], arow[j], acc[j]);
            }
        }
        // final flush for the chunk
        {
            float* dst = g_new_bonds + cur * N_BASIS;
            #pragma unroll
            for (int j = 0; j < N_BASIS; j++) atomicAdd(dst + j, acc[j]);
        }
    }
}

// ---------------------------------------------------------------------------
// Kernel 3: out = edge_feat + silu(nb@W_gate+b_gate) * sigmoid(nb@W_sig+b_sig)
// One warp per edge; weights loop-invariant in registers (72 floats/thread).
// Lane handles columns {lane, lane+32, lane+64, lane+96}.
// ---------------------------------------------------------------------------
#define TPB_C 256

__global__ __launch_bounds__(TPB_C) void mlp_kernel(
    const float* __restrict__ edge_feat,
    const float* __restrict__ W_gate, const float* __restrict__ b_gate,
    const float* __restrict__ W_sig,  const float* __restrict__ b_sig,
    float* __restrict__ out) {

    int lane   = threadIdx.x & 31;
    int warp   = (blockIdx.x * TPB_C + threadIdx.x) >> 5;
    int nwarps = (gridDim.x * TPB_C) >> 5;

    float wg[4][N_BASIS], ws[4][N_BASIS], bg[4], bs[4];
    #pragma unroll
    for (int m = 0; m < 4; m++) {
        int j = lane + 32 * m;
        bg[m] = b_gate[j];
        bs[m] = b_sig[j];
        #pragma unroll
        for (int k = 0; k < N_BASIS; k++) {
            wg[m][k] = W_gate[k * D_EDGE + j];
            ws[m][k] = W_sig[k * D_EDGE + j];
        }
    }

    for (int e = warp; e < N_EDGES; e += nwarps) {
        float nb[N_BASIS];
        #pragma unroll
        for (int k = 0; k < N_BASIS; k++) nb[k] = g_new_bonds[e * N_BASIS + k];

        #pragma unroll
        for (int m = 0; m < 4; m++) {
            float g = bg[m], s = bs[m];
            #pragma unroll
            for (int k = 0; k < N_BASIS; k++) {
                g = fmaf(nb[k], wg[m][k], g);
                s = fmaf(nb[k], ws[m][k], s);
            }
            float sg = 1.f / (1.f + __expf(-g));   // sigmoid(g)
            float ss = 1.f / (1.f + __expf(-s));   // sigmoid(s)
            float up = g * sg * ss;                 // silu(g) * sigmoid(s)
            int j = lane + 32 * m;
            int idx = e * D_EDGE + j;
            out[idx] = edge_feat[idx] + up;
        }
    }
}

// ---------------------------------------------------------------------------
// Launch
// Input order (metadata): node_feat, edge_feat, three_basis, three_cutoff,
// W_atom, b_atom, W_gate, b_gate, W_sig, b_sig, graph_dst, lg_src, lg_dst,
// segment_ids.  (three_cutoff and lg_src are dead code in the reference.)
// ---------------------------------------------------------------------------
extern "C" void kernel_launch(void* const* d_in, const int* in_sizes, int n_in,
                              void* d_out, int out_size) {
    const float* node_feat   = (const float*)d_in[0];
    const float* edge_feat   = (const float*)d_in[1];
    const float* three_basis = (const float*)d_in[2];
    const float* W_atom      = (const float*)d_in[4];
    const float* b_atom      = (const float*)d_in[5];
    const float* W_gate      = (const float*)d_in[6];
    const float* b_gate      = (const float*)d_in[7];
    const float* W_sig       = (const float*)d_in[8];
    const float* b_sig       = (const float*)d_in[9];
    const int*   graph_dst   = (const int*)d_in[10];
    const int*   lg_dst      = (const int*)d_in[12];
    const int*   seg_ids     = (const int*)d_in[13];
    float*       out         = (float*)d_out;

    const int smem_bytes = N_ATOMS * N_BASIS * sizeof(float);  // 180000
    cudaFuncSetAttribute(triples_kernel,
                         cudaFuncAttributeMaxDynamicSharedMemorySize, smem_bytes);

    zero_bonds_kernel<<<(450000 + 255) / 256, 256>>>();
    atoms_kernel<<<(N_ATOMS * N_BASIS + 255) / 256, 256>>>(node_feat, W_atom, b_atom);
    triples_kernel<<<GRID_B, TPB_B, smem_bytes>>>(three_basis, graph_dst, lg_dst, seg_ids);
    mlp_kernel<<<1184, TPB_C>>>(edge_feat, W_gate, b_gate, W_sig, b_sig, out);
}

// round 2
// speedup vs baseline: 1.4188x; 1.4188x over previous
#include <cuda_runtime.h>
#include <cuda_bf16.h>

#define N_ATOMS   5000
#define N_EDGES   200000
#define N_TRIPLES 4000000
#define D_NODE    128
#define D_EDGE    128
#define N_BASIS   9

// Scratch (no allocations allowed)
__device__ float g_atoms[N_ATOMS * N_BASIS];        // sigmoid(node@W_atom+b)  [5000 x 9]
__device__ float g_new_bonds[N_EDGES * N_BASIS];    // segment sums            [200000 x 9]

// ---------------------------------------------------------------------------
// Kernel 0: zero the segment-sum accumulator
// ---------------------------------------------------------------------------
__global__ void zero_bonds_kernel() {
    int i = blockIdx.x * blockDim.x + threadIdx.x;
    const int n4 = (N_EDGES * N_BASIS) / 4;  // 450000
    if (i < n4) reinterpret_cast<float4*>(g_new_bonds)[i] = make_float4(0.f, 0.f, 0.f, 0.f);
}

// ---------------------------------------------------------------------------
// Kernel 1: atoms = sigmoid(node_feat @ W_atom + b_atom)   [5000 x 9]
// ---------------------------------------------------------------------------
__global__ void atoms_kernel(const float* __restrict__ node_feat,
                             const float* __restrict__ W_atom,
                             const float* __restrict__ b_atom) {
    int id = blockIdx.x * blockDim.x + threadIdx.x;
    if (id >= N_ATOMS * N_BASIS) return;
    int a = id / N_BASIS;
    int j = id % N_BASIS;
    float acc = b_atom[j];
    const float* nf = node_feat + a * D_NODE;
    #pragma unroll 8
    for (int k = 0; k < D_NODE; k++)
        acc = fmaf(nf[k], W_atom[k * N_BASIS + j], acc);
    g_atoms[id] = 1.0f / (1.0f + __expf(-acc));
}

// ---------------------------------------------------------------------------
// Kernel 2: basis = three_basis * atoms[graph_dst[lg_dst]]; segment_sum
// (unchanged from R1: shared atoms table + register run-accumulation)
// ---------------------------------------------------------------------------
#define TPB_B   512
#define GRID_B  148
#define CHUNK   16
#define NCHUNKS (N_TRIPLES / CHUNK)   // 250000, exact

__global__ __launch_bounds__(TPB_B) void triples_kernel(
    const float* __restrict__ three_basis,
    const int*   __restrict__ graph_dst,
    const int*   __restrict__ lg_dst,
    const int*   __restrict__ seg_ids) {

    extern __shared__ float s_atoms[];  // 45000 floats = 180000 bytes
    for (int i = threadIdx.x; i < N_ATOMS * N_BASIS; i += TPB_B)
        s_atoms[i] = g_atoms[i];
    __syncthreads();

    const float4* tb4 = reinterpret_cast<const float4*>(three_basis);
    const int4*   lg4 = reinterpret_cast<const int4*>(lg_dst);
    const int4*   sg4 = reinterpret_cast<const int4*>(seg_ids);

    int tid = blockIdx.x * TPB_B + threadIdx.x;
    const int stride = GRID_B * TPB_B;

    for (int chunk = tid; chunk < NCHUNKS; chunk += stride) {
        float acc[N_BASIS];
        #pragma unroll
        for (int j = 0; j < N_BASIS; j++) acc[j] = 0.f;
        int cur = -1;

        #pragma unroll
        for (int s = 0; s < 4; s++) {           // 4 subgroups of 4 triples
            int4 lg = lg4[chunk * 4 + s];
            int4 sg = sg4[chunk * 4 + s];
            int eis[4];
            eis[0] = graph_dst[lg.x];
            eis[1] = graph_dst[lg.y];
            eis[2] = graph_dst[lg.z];
            eis[3] = graph_dst[lg.w];
            int segs[4] = {sg.x, sg.y, sg.z, sg.w};

            float v[36];
            #pragma unroll
            for (int i = 0; i < 9; i++) {
                float4 t = tb4[chunk * 36 + s * 9 + i];
                v[i * 4 + 0] = t.x; v[i * 4 + 1] = t.y;
                v[i * 4 + 2] = t.z; v[i * 4 + 3] = t.w;
            }

            #pragma unroll
            for (int t = 0; t < 4; t++) {
                int e = segs[t];
                if (e != cur) {
                    if (cur >= 0) {
                        float* dst = g_new_bonds + cur * N_BASIS;
                        #pragma unroll
                        for (int j = 0; j < N_BASIS; j++) atomicAdd(dst + j, acc[j]);
                        #pragma unroll
                        for (int j = 0; j < N_BASIS; j++) acc[j] = 0.f;
                    }
                    cur = e;
                }
                const float* arow = s_atoms + eis[t] * N_BASIS;
                #pragma unroll
                for (int j = 0; j < N_BASIS; j++)
                    acc[j] = fmaf(v[t * 9 + j], arow[j], acc[j]);
            }
        }
        {
            float* dst = g_new_bonds + cur * N_BASIS;
            #pragma unroll
            for (int j = 0; j < N_BASIS; j++) atomicAdd(dst + j, acc[j]);
        }
    }
}

// ---------------------------------------------------------------------------
// Kernel 3 (REWRITTEN): out = edge_feat + silu(nb@W_gate+b_gate)*sigmoid(nb@W_sig+b_sig)
//
// Thread = one output column (j in [0,128)), block = 128 threads.
// Block handles a tile of E_TILE=64 edges:
//   - nb tile (64x9) cooperatively staged in smem (coalesced)
//   - per-edge nb reads are same-address smem broadcasts
//   - only 20 weight floats per thread -> ~40 regs -> high occupancy
//   - edge_feat load / out store perfectly coalesced
// ---------------------------------------------------------------------------
#define E_TILE  64
#define NB_TILE (E_TILE * N_BASIS)   // 576 floats

__global__ __launch_bounds__(D_EDGE) void mlp_kernel(
    const float* __restrict__ edge_feat,
    const float* __restrict__ W_gate, const float* __restrict__ b_gate,
    const float* __restrict__ W_sig,  const float* __restrict__ b_sig,
    float* __restrict__ out) {

    __shared__ float s_nb[NB_TILE];

    const int j  = threadIdx.x;            // column
    const int e0 = blockIdx.x * E_TILE;    // first edge of tile

    // stage nb tile (coalesced: 576 consecutive floats)
    const float* nb_src = g_new_bonds + (size_t)e0 * N_BASIS;
    #pragma unroll
    for (int i = j; i < NB_TILE; i += D_EDGE)
        s_nb[i] = nb_src[i];

    // per-thread column weights (L2-resident, coalesced across threads)
    float wg[N_BASIS], ws[N_BASIS];
    #pragma unroll
    for (int k = 0; k < N_BASIS; k++) {
        wg[k] = W_gate[k * D_EDGE + j];
        ws[k] = W_sig [k * D_EDGE + j];
    }
    const float bg = b_gate[j];
    const float bs = b_sig[j];

    __syncthreads();

    #pragma unroll 4
    for (int e = 0; e < E_TILE; e++) {
        const float* nb = s_nb + e * N_BASIS;   // broadcast reads
        float g = bg, s = bs;
        #pragma unroll
        for (int k = 0; k < N_BASIS; k++) {
            float n = nb[k];
            g = fmaf(n, wg[k], g);
            s = fmaf(n, ws[k], s);
        }
        float sg = 1.f / (1.f + __expf(-g));
        float ss = 1.f / (1.f + __expf(-s));
        float up = g * sg * ss;                 // silu(g) * sigmoid(s)
        size_t idx = (size_t)(e0 + e) * D_EDGE + j;
        out[idx] = edge_feat[idx] + up;
    }
}

// ---------------------------------------------------------------------------
// Launch
// ---------------------------------------------------------------------------
extern "C" void kernel_launch(void* const* d_in, const int* in_sizes, int n_in,
                              void* d_out, int out_size) {
    const float* node_feat   = (const float*)d_in[0];
    const float* edge_feat   = (const float*)d_in[1];
    const float* three_basis = (const float*)d_in[2];
    const float* W_atom      = (const float*)d_in[4];
    const float* b_atom      = (const float*)d_in[5];
    const float* W_gate      = (const float*)d_in[6];
    const float* b_gate      = (const float*)d_in[7];
    const float* W_sig       = (const float*)d_in[8];
    const float* b_sig       = (const float*)d_in[9];
    const int*   graph_dst   = (const int*)d_in[10];
    const int*   lg_dst      = (const int*)d_in[12];
    const int*   seg_ids     = (const int*)d_in[13];
    float*       out         = (float*)d_out;

    const int smem_bytes = N_ATOMS * N_BASIS * sizeof(float);  // 180000
    cudaFuncSetAttribute(triples_kernel,
                         cudaFuncAttributeMaxDynamicSharedMemorySize, smem_bytes);

    zero_bonds_kernel<<<(450000 + 255) / 256, 256>>>();
    atoms_kernel<<<(N_ATOMS * N_BASIS + 255) / 256, 256>>>(node_feat, W_atom, b_atom);
    triples_kernel<<<GRID_B, TPB_B, smem_bytes>>>(three_basis, graph_dst, lg_dst, seg_ids);
    mlp_kernel<<<N_EDGES / E_TILE, D_EDGE>>>(edge_feat, W_gate, b_gate, W_sig, b_sig, out);
}

// round 3
// speedup vs baseline: 1.8929x; 1.3342x over previous
#include <cuda_runtime.h>
#include <cuda_bf16.h>

#define N_ATOMS   5000
#define N_EDGES   200000
#define N_TRIPLES 4000000
#define D_NODE    128
#define D_EDGE    128
#define N_BASIS   9

// Scratch (no allocations allowed)
__device__ float g_atoms[N_ATOMS * N_BASIS];        // sigmoid(node@W_atom+b)  [5000 x 9]
__device__ float g_new_bonds[N_EDGES * N_BASIS];    // segment sums            [200000 x 9]

// ---------------------------------------------------------------------------
// Kernel 0: zero the segment-sum accumulator
// ---------------------------------------------------------------------------
__global__ void zero_bonds_kernel() {
    int i = blockIdx.x * blockDim.x + threadIdx.x;
    const int n4 = (N_EDGES * N_BASIS) / 4;  // 450000
    if (i < n4) reinterpret_cast<float4*>(g_new_bonds)[i] = make_float4(0.f, 0.f, 0.f, 0.f);
}

// ---------------------------------------------------------------------------
// Kernel 1: atoms = sigmoid(node_feat @ W_atom + b_atom)   [5000 x 9]
// ---------------------------------------------------------------------------
__global__ void atoms_kernel(const float* __restrict__ node_feat,
                             const float* __restrict__ W_atom,
                             const float* __restrict__ b_atom) {
    int id = blockIdx.x * blockDim.x + threadIdx.x;
    if (id >= N_ATOMS * N_BASIS) return;
    int a = id / N_BASIS;
    int j = id % N_BASIS;
    float acc = b_atom[j];
    const float* nf = node_feat + a * D_NODE;
    #pragma unroll 8
    for (int k = 0; k < D_NODE; k++)
        acc = fmaf(nf[k], W_atom[k * N_BASIS + j], acc);
    g_atoms[id] = 1.0f / (1.0f + __expf(-acc));
}

// ---------------------------------------------------------------------------
// Kernel 2: basis = three_basis * atoms[graph_dst[lg_dst]]; segment_sum
// (unchanged: shared atoms table + register run-accumulation)
// ---------------------------------------------------------------------------
#define TPB_B   512
#define GRID_B  148
#define CHUNK   16
#define NCHUNKS (N_TRIPLES / CHUNK)   // 250000, exact

__global__ __launch_bounds__(TPB_B) void triples_kernel(
    const float* __restrict__ three_basis,
    const int*   __restrict__ graph_dst,
    const int*   __restrict__ lg_dst,
    const int*   __restrict__ seg_ids) {

    extern __shared__ float s_atoms[];  // 45000 floats = 180000 bytes
    for (int i = threadIdx.x; i < N_ATOMS * N_BASIS; i += TPB_B)
        s_atoms[i] = g_atoms[i];
    __syncthreads();

    const float4* tb4 = reinterpret_cast<const float4*>(three_basis);
    const int4*   lg4 = reinterpret_cast<const int4*>(lg_dst);
    const int4*   sg4 = reinterpret_cast<const int4*>(seg_ids);

    int tid = blockIdx.x * TPB_B + threadIdx.x;
    const int stride = GRID_B * TPB_B;

    for (int chunk = tid; chunk < NCHUNKS; chunk += stride) {
        float acc[N_BASIS];
        #pragma unroll
        for (int j = 0; j < N_BASIS; j++) acc[j] = 0.f;
        int cur = -1;

        #pragma unroll
        for (int s = 0; s < 4; s++) {           // 4 subgroups of 4 triples
            int4 lg = lg4[chunk * 4 + s];
            int4 sg = sg4[chunk * 4 + s];
            int eis[4];
            eis[0] = graph_dst[lg.x];
            eis[1] = graph_dst[lg.y];
            eis[2] = graph_dst[lg.z];
            eis[3] = graph_dst[lg.w];
            int segs[4] = {sg.x, sg.y, sg.z, sg.w};

            float v[36];
            #pragma unroll
            for (int i = 0; i < 9; i++) {
                float4 t = tb4[chunk * 36 + s * 9 + i];
                v[i * 4 + 0] = t.x; v[i * 4 + 1] = t.y;
                v[i * 4 + 2] = t.z; v[i * 4 + 3] = t.w;
            }

            #pragma unroll
            for (int t = 0; t < 4; t++) {
                int e = segs[t];
                if (e != cur) {
                    if (cur >= 0) {
                        float* dst = g_new_bonds + cur * N_BASIS;
                        #pragma unroll
                        for (int j = 0; j < N_BASIS; j++) atomicAdd(dst + j, acc[j]);
                        #pragma unroll
                        for (int j = 0; j < N_BASIS; j++) acc[j] = 0.f;
                    }
                    cur = e;
                }
                const float* arow = s_atoms + eis[t] * N_BASIS;
                #pragma unroll
                for (int j = 0; j < N_BASIS; j++)
                    acc[j] = fmaf(v[t * 9 + j], arow[j], acc[j]);
            }
        }
        {
            float* dst = g_new_bonds + cur * N_BASIS;
            #pragma unroll
            for (int j = 0; j < N_BASIS; j++) atomicAdd(dst + j, acc[j]);
        }
    }
}

// ---------------------------------------------------------------------------
// Kernel 3: out = edge_feat + silu(nb@W_gate+b_gate)*sigmoid(nb@W_sig+b_sig)
//
// PERSISTENT version. 1184 blocks x 128 threads (8 blocks/SM, 32 warps/SM).
// Thread = output column j. Block grid-strides over tiles of 64 edges.
// Column weights loaded into registers ONCE per block. Inner loop processes
// edge PAIRS (4 independent FMA chains + 4 MUFU chains) to cover latency.
// ---------------------------------------------------------------------------
#define E_TILE   64
#define NB_TILE  (E_TILE * N_BASIS)            // 576 floats
#define N_TILES  (N_EDGES / E_TILE)            // 3125
#define MLP_GRID 1184                          // 8 blocks/SM * 148

__global__ __launch_bounds__(D_EDGE) void mlp_kernel(
    const float* __restrict__ edge_feat,
    const float* __restrict__ W_gate, const float* __restrict__ b_gate,
    const float* __restrict__ W_sig,  const float* __restrict__ b_sig,
    float* __restrict__ out) {

    __shared__ float s_nb[NB_TILE];

    const int j = threadIdx.x;                 // column

    // Per-thread column weights: loaded once per (persistent) block.
    float wg[N_BASIS], ws[N_BASIS];
    #pragma unroll
    for (int k = 0; k < N_BASIS; k++) {
        wg[k] = W_gate[k * D_EDGE + j];
        ws[k] = W_sig [k * D_EDGE + j];
    }
    const float bg = b_gate[j];
    const float bs = b_sig[j];

    for (int tile = blockIdx.x; tile < N_TILES; tile += MLP_GRID) {
        const int e0 = tile * E_TILE;

        __syncthreads();   // protect s_nb reuse from previous tile
        const float* nb_src = g_new_bonds + (size_t)e0 * N_BASIS;
        #pragma unroll
        for (int i = j; i < NB_TILE; i += D_EDGE)
            s_nb[i] = nb_src[i];
        __syncthreads();

        #pragma unroll 2
        for (int e = 0; e < E_TILE; e += 2) {
            const float* nb0 = s_nb + e * N_BASIS;
            const float* nb1 = nb0 + N_BASIS;

            // prefetch residual inputs (coalesced)
            size_t idx0 = (size_t)(e0 + e) * D_EDGE + j;
            size_t idx1 = idx0 + D_EDGE;
            float ef0 = edge_feat[idx0];
            float ef1 = edge_feat[idx1];

            float g0 = bg, s0 = bs, g1 = bg, s1 = bs;
            #pragma unroll
            for (int k = 0; k < N_BASIS; k++) {
                float n0 = nb0[k], n1 = nb1[k];
                g0 = fmaf(n0, wg[k], g0);
                s0 = fmaf(n0, ws[k], s0);
                g1 = fmaf(n1, wg[k], g1);
                s1 = fmaf(n1, ws[k], s1);
            }
            float sg0 = 1.f / (1.f + __expf(-g0));
            float ss0 = 1.f / (1.f + __expf(-s0));
            float sg1 = 1.f / (1.f + __expf(-g1));
            float ss1 = 1.f / (1.f + __expf(-s1));
            out[idx0] = ef0 + g0 * sg0 * ss0;
            out[idx1] = ef1 + g1 * sg1 * ss1;
        }
    }
}

// ---------------------------------------------------------------------------
// Launch
// ---------------------------------------------------------------------------
extern "C" void kernel_launch(void* const* d_in, const int* in_sizes, int n_in,
                              void* d_out, int out_size) {
    const float* node_feat   = (const float*)d_in[0];
    const float* edge_feat   = (const float*)d_in[1];
    const float* three_basis = (const float*)d_in[2];
    const float* W_atom      = (const float*)d_in[4];
    const float* b_atom      = (const float*)d_in[5];
    const float* W_gate      = (const float*)d_in[6];
    const float* b_gate      = (const float*)d_in[7];
    const float* W_sig       = (const float*)d_in[8];
    const float* b_sig       = (const float*)d_in[9];
    const int*   graph_dst   = (const int*)d_in[10];
    const int*   lg_dst      = (const int*)d_in[12];
    const int*   seg_ids     = (const int*)d_in[13];
    float*       out         = (float*)d_out;

    const int smem_bytes = N_ATOMS * N_BASIS * sizeof(float);  // 180000
    cudaFuncSetAttribute(triples_kernel,
                         cudaFuncAttributeMaxDynamicSharedMemorySize, smem_bytes);

    zero_bonds_kernel<<<(450000 + 255) / 256, 256>>>();
    atoms_kernel<<<(N_ATOMS * N_BASIS + 255) / 256, 256>>>(node_feat, W_atom, b_atom);
    triples_kernel<<<GRID_B, TPB_B, smem_bytes>>>(three_basis, graph_dst, lg_dst, seg_ids);
    mlp_kernel<<<MLP_GRID, D_EDGE>>>(edge_feat, W_gate, b_gate, W_sig, b_sig, out);
}